// round 3
// baseline (speedup 1.0000x reference)
#include <cuda_runtime.h>
#include <cuda_bf16.h>

#define Cc   9
#define KSc  9
#define OUTc 16
#define NBc  16
#define Vc   20000
#define Bc   2
#define LPG  4           // lanes per vertex group

__global__ __launch_bounds__(128)
void nlayer_kernel(const float* __restrict__ x,
                   const float* __restrict__ W,
                   const int*   __restrict__ adj,
                   float*       __restrict__ out)
{
    __shared__ float Wsh[Cc * KSc * OUTc];   // 1296 floats
    for (int i = threadIdx.x; i < Cc * KSc * OUTc; i += blockDim.x)
        Wsh[i] = W[i];
    __syncthreads();

    int tid   = blockIdx.x * blockDim.x + threadIdx.x;
    int group = tid >> 2;          // vertex index over B*V
    int p     = tid & 3;           // lane's k-slice: k = 4j + p
    if (group >= Bc * Vc) return;

    int b = group / Vc;
    int v = group - b * Vc;
    const float* xb = x + (size_t)b * Vc * Cc;

    // center vertex features (all 4 lanes: same address -> merged request)
    float xv[Cc];
    #pragma unroll
    for (int c = 0; c < Cc; c++) xv[c] = __ldg(&xb[(size_t)v * Cc + c]);

    // adjacency row
    int a[NBc];
    const int4* adj4 = reinterpret_cast<const int4*>(adj + (size_t)v * NBc);
    #pragma unroll
    for (int i = 0; i < NBc / 4; i++) {
        int4 t = __ldg(&adj4[i]);
        a[i*4+0] = t.x; a[i*4+1] = t.y; a[i*4+2] = t.z; a[i*4+3] = t.w;
    }

    // s[j][c] for this lane's k-slots (k = 4j + p)
    float s[3][Cc];
    #pragma unroll
    for (int j = 0; j < 3; j++)
        #pragma unroll
        for (int c = 0; c < Cc; c++) s[j][c] = 0.0f;

    int deg = 0;

    #pragma unroll
    for (int n = 0; n < NBc; n++) {
        int an    = a[n];
        int valid = (an != 0);
        deg += valid;
        int ridx = valid ? (an - 1) : 0;

        const float* nr = xb + (size_t)ridx * Cc;
        float nbv[Cc], d[Cc];
        #pragma unroll
        for (int c = 0; c < Cc; c++) {
            nbv[c] = __ldg(&nr[c]);
            d[c]   = xv[c] - nbv[c];
        }

        // softmax over 9 channels (replicated across the 4 lanes; cheap)
        float m = d[0];
        #pragma unroll
        for (int c = 1; c < Cc; c++) m = fmaxf(m, d[c]);
        float e[Cc], sum = 0.0f;
        #pragma unroll
        for (int c = 0; c < Cc; c++) { e[c] = __expf(d[c] - m); sum += e[c]; }
        float inv = __fdividef(1.0f, sum);
        float msk = valid ? inv : 0.0f;

        // lane's q values: q_{4j+p}; j=2 only valid for p==0 (k=8)
        float q0 = ((p == 0) ? e[0] : (p == 1) ? e[1] : (p == 2) ? e[2] : e[3]) * msk;
        float q1 = ((p == 0) ? e[4] : (p == 1) ? e[5] : (p == 2) ? e[6] : e[7]) * msk;
        float q2 = ((p == 0) ? e[8] * msk : 0.0f);

        #pragma unroll
        for (int c = 0; c < Cc; c++) {
            s[0][c] = fmaf(q0, nbv[c], s[0][c]);
            s[1][c] = fmaf(q1, nbv[c], s[1][c]);
            s[2][c] = fmaf(q2, nbv[c], s[2][c]);
        }
    }

    float invdeg = (deg > 0) ? (1.0f / (float)deg) : 0.0f;

    // partial contraction over this lane's k-slots
    float acc[OUTc];
    #pragma unroll
    for (int o = 0; o < OUTc; o++) acc[o] = 0.0f;

    #pragma unroll
    for (int j = 0; j < 3; j++) {
        int k = 4 * j + p;
        if (k > 8) k = 8;            // s[2][*]==0 for p!=0, value irrelevant
        #pragma unroll
        for (int c = 0; c < Cc; c++) {
            float sc = s[j][c];
            const float* wrow = &Wsh[(c * KSc + k) * OUTc];
            #pragma unroll
            for (int o = 0; o < OUTc; o++)
                acc[o] = fmaf(sc, wrow[o], acc[o]);
        }
    }

    // butterfly-sum acc over the 4-lane group
    #pragma unroll
    for (int o = 0; o < OUTc; o++) {
        acc[o] += __shfl_xor_sync(0xffffffffu, acc[o], 1);
        acc[o] += __shfl_xor_sync(0xffffffffu, acc[o], 2);
    }

    // lane p stores outputs [4p, 4p+4)  -> coalesced 64B per group
    float4 r;
    r.x = (p == 0) ? acc[0]  : (p == 1) ? acc[4]  : (p == 2) ? acc[8]  : acc[12];
    r.y = (p == 0) ? acc[1]  : (p == 1) ? acc[5]  : (p == 2) ? acc[9]  : acc[13];
    r.z = (p == 0) ? acc[2]  : (p == 1) ? acc[6]  : (p == 2) ? acc[10] : acc[14];
    r.w = (p == 0) ? acc[3]  : (p == 1) ? acc[7]  : (p == 2) ? acc[11] : acc[15];
    r.x = fmaxf(r.x * invdeg, 0.0f);
    r.y = fmaxf(r.y * invdeg, 0.0f);
    r.z = fmaxf(r.z * invdeg, 0.0f);
    r.w = fmaxf(r.w * invdeg, 0.0f);

    *reinterpret_cast<float4*>(out + (size_t)group * OUTc + p * 4) = r;
}

extern "C" void kernel_launch(void* const* d_in, const int* in_sizes, int n_in,
                              void* d_out, int out_size)
{
    const float* x   = (const float*)d_in[0];   // (2, 20000, 9)
    const float* W   = (const float*)d_in[1];   // (9, 9, 16)
    const int*   adj = (const int*)d_in[2];     // (20000, 16)
    float*       out = (float*)d_out;           // (2, 20000, 16)

    const int total   = Bc * Vc * LPG;          // 160000
    const int threads = 128;
    const int blocks  = (total + threads - 1) / threads;  // 1250
    nlayer_kernel<<<blocks, threads>>>(x, W, adj, out);
}

// round 4
// speedup vs baseline: 1.2373x; 1.2373x over previous
#include <cuda_runtime.h>
#include <cuda_bf16.h>

#define Cc   9
#define KSc  9
#define OUTc 16
#define NBc  16
#define Vc   20000
#define Bc   2
#define LPG  4           // lanes per vertex; lane p owns neighbors 4p..4p+3

__global__ __launch_bounds__(128)
void nlayer_kernel(const float* __restrict__ x,
                   const float* __restrict__ W,
                   const int*   __restrict__ adj,
                   float*       __restrict__ out)
{
    __shared__ float Wsh[Cc * KSc * OUTc];   // 1296 floats
    for (int i = threadIdx.x; i < Cc * KSc * OUTc; i += blockDim.x)
        Wsh[i] = W[i];
    __syncthreads();

    int tid   = blockIdx.x * blockDim.x + threadIdx.x;
    int group = tid >> 2;          // vertex index over B*V
    int p     = tid & 3;           // neighbor quarter + output slice
    if (group >= Bc * Vc) return;  // never taken: 160000 % 128 == 0

    int b = group / Vc;
    int v = group - b * Vc;
    const float* xb = x + (size_t)b * Vc * Cc;

    // center vertex features (4 lanes hit same addresses -> merged)
    float xv[Cc];
    #pragma unroll
    for (int c = 0; c < Cc; c++) xv[c] = __ldg(&xb[(size_t)v * Cc + c]);

    // this lane's 4 neighbors: one int4, coalesced 64B per group
    int4 av = __ldg(reinterpret_cast<const int4*>(adj + (size_t)v * NBc) + p);
    int a[4] = {av.x, av.y, av.z, av.w};

    // partial s[k][c] over this lane's 4 neighbors
    float s[KSc][Cc];
    #pragma unroll
    for (int k = 0; k < KSc; k++)
        #pragma unroll
        for (int c = 0; c < Cc; c++) s[k][c] = 0.0f;

    int deg = 0;

    #pragma unroll
    for (int n = 0; n < 4; n++) {
        int an    = a[n];
        int valid = (an != 0);
        deg += valid;
        int ridx = valid ? (an - 1) : 0;

        const float* nr = xb + (size_t)ridx * Cc;
        float nbv[Cc], d[Cc];
        #pragma unroll
        for (int c = 0; c < Cc; c++) {
            nbv[c] = __ldg(&nr[c]);
            d[c]   = xv[c] - nbv[c];
        }

        // softmax over 9 channels — computed once per neighbor
        float m = d[0];
        #pragma unroll
        for (int c = 1; c < Cc; c++) m = fmaxf(m, d[c]);
        float e[Cc], sum = 0.0f;
        #pragma unroll
        for (int c = 0; c < Cc; c++) { e[c] = __expf(d[c] - m); sum += e[c]; }
        float inv = __fdividef(1.0f, sum);
        float msk = valid ? inv : 0.0f;

        #pragma unroll
        for (int k = 0; k < KSc; k++) {
            float qk = e[k] * msk;
            #pragma unroll
            for (int c = 0; c < Cc; c++)
                s[k][c] = fmaf(qk, nbv[c], s[k][c]);
        }
    }

    // reduce partial s and deg across the 4-lane group
    deg += __shfl_xor_sync(0xffffffffu, deg, 1);
    deg += __shfl_xor_sync(0xffffffffu, deg, 2);
    #pragma unroll
    for (int k = 0; k < KSc; k++)
        #pragma unroll
        for (int c = 0; c < Cc; c++) {
            float t = s[k][c];
            t += __shfl_xor_sync(0xffffffffu, t, 1);
            t += __shfl_xor_sync(0xffffffffu, t, 2);
            s[k][c] = t;
        }

    float invdeg = (deg > 0) ? (1.0f / (float)deg) : 0.0f;

    // lane p contracts its output slice o = 4p..4p+3 over the FULL s
    float4 acc = make_float4(0.0f, 0.0f, 0.0f, 0.0f);
    const int obase = p * 4;

    #pragma unroll
    for (int c = 0; c < Cc; c++) {
        #pragma unroll
        for (int k = 0; k < KSc; k++) {
            float sc = s[k][c];
            float4 w = *reinterpret_cast<const float4*>(
                           &Wsh[(c * KSc + k) * OUTc + obase]);  // 16B-aligned LDS.128
            acc.x = fmaf(sc, w.x, acc.x);
            acc.y = fmaf(sc, w.y, acc.y);
            acc.z = fmaf(sc, w.z, acc.z);
            acc.w = fmaf(sc, w.w, acc.w);
        }
    }

    float4 r;
    r.x = fmaxf(acc.x * invdeg, 0.0f);
    r.y = fmaxf(acc.y * invdeg, 0.0f);
    r.z = fmaxf(acc.z * invdeg, 0.0f);
    r.w = fmaxf(acc.w * invdeg, 0.0f);

    *reinterpret_cast<float4*>(out + (size_t)group * OUTc + obase) = r;
}

extern "C" void kernel_launch(void* const* d_in, const int* in_sizes, int n_in,
                              void* d_out, int out_size)
{
    const float* x   = (const float*)d_in[0];   // (2, 20000, 9)
    const float* W   = (const float*)d_in[1];   // (9, 9, 16)
    const int*   adj = (const int*)d_in[2];     // (20000, 16)
    float*       out = (float*)d_out;           // (2, 20000, 16)

    const int total   = Bc * Vc * LPG;          // 160000
    const int threads = 128;
    const int blocks  = (total + threads - 1) / threads;  // 1250
    nlayer_kernel<<<blocks, threads>>>(x, W, adj, out);
}